// round 1
// baseline (speedup 1.0000x reference)
#include <cuda_runtime.h>

// WaveletTree: 3-level gated Haar DWT/IDWT tree.
// x: [B,C,224,224] f32 -> out: [B,C,112,112] f32.
// Block-local: each aligned 8x8 input tile fully determines a 4x4 output tile,
// except for 9 global gate scalars (max|subband| > thr).
// Fast path (all gates on): out = 2 * x[:,:,1::2,1::2].

namespace {
constexpr int HDIM = 224;
constexpr int WDIM = 224;
constexpr int OH   = 112;
constexpr int OW   = 112;
constexpr int TX   = 28;   // tiles per row (224/8)
constexpr int TY   = 28;   // tiles per col
constexpr int TPB  = TX * TY;  // tiles per (b,c) plane
}

// abs-max accumulators (float bits as int; valid for non-negative floats)
// order: [lh1, hl1, hh1, lh2, hl2, hh2, lh3, hl3, hh3]
__device__ int g_absmax[9];

__global__ void wt_init() {
    if (threadIdx.x < 9) g_absmax[threadIdx.x] = 0;
}

__device__ __forceinline__ float warp_max(float v) {
#pragma unroll
    for (int o = 16; o; o >>= 1)
        v = fmaxf(v, __shfl_xor_sync(0xffffffffu, v, o));
    return v;
}

// ---------------------------------------------------------------------------
// Pass 1: per-tile subband abs-max reduction + speculative fast-path output.
// One thread per 8x8 tile. 256 threads/block.
// ---------------------------------------------------------------------------
__global__ __launch_bounds__(256, 2) void wt_pass1(const float* __restrict__ x,
                                                   float* __restrict__ out,
                                                   int total_tiles) {
    int t = blockIdx.x * 256 + threadIdx.x;

    float mx[9];
#pragma unroll
    for (int k = 0; k < 9; k++) mx[k] = 0.0f;

    if (t < total_tiles) {
        int tx = t % TX;
        int r  = t / TX;
        int ty = r % TY;
        int bc = r / TY;

        const float* xp = x + (size_t)bc * (HDIM * WDIM)
                            + (size_t)(ty * 8) * WDIM + tx * 8;

        float xv[8][8];
#pragma unroll
        for (int rr = 0; rr < 8; rr++) {
            float4 a = *reinterpret_cast<const float4*>(xp + rr * WDIM);
            float4 b = *reinterpret_cast<const float4*>(xp + rr * WDIM + 4);
            xv[rr][0] = a.x; xv[rr][1] = a.y; xv[rr][2] = a.z; xv[rr][3] = a.w;
            xv[rr][4] = b.x; xv[rr][5] = b.y; xv[rr][6] = b.z; xv[rr][7] = b.w;
        }

        // Speculative fast-path output: out = 2 * x[1::2, 1::2]
        float* op = out + (size_t)bc * (OH * OW)
                        + (size_t)(ty * 4) * OW + tx * 4;
#pragma unroll
        for (int rr = 0; rr < 4; rr++) {
            float4 o;
            o.x = 2.0f * xv[2 * rr + 1][1];
            o.y = 2.0f * xv[2 * rr + 1][3];
            o.z = 2.0f * xv[2 * rr + 1][5];
            o.w = 2.0f * xv[2 * rr + 1][7];
            *reinterpret_cast<float4*>(op + rr * OW) = o;
        }

        // Level 1
        float ll1[4][4];
#pragma unroll
        for (int i = 0; i < 4; i++) {
#pragma unroll
            for (int j = 0; j < 4; j++) {
                float x00 = xv[2*i][2*j],     x01 = xv[2*i][2*j+1];
                float x10 = xv[2*i+1][2*j],   x11 = xv[2*i+1][2*j+1];
                float s0 = x00 + x01, s1 = x10 + x11;
                float d0 = x01 - x00, d1 = x11 - x10;
                ll1[i][j] = (s0 + s1) * 0.5f;
                mx[0] = fmaxf(mx[0], fabsf((s1 - s0) * 0.5f));
                mx[1] = fmaxf(mx[1], fabsf((d0 + d1) * 0.5f));
                mx[2] = fmaxf(mx[2], fabsf((d1 - d0) * 0.5f));
            }
        }

        // Level 2
        float ll2[2][2];
#pragma unroll
        for (int i = 0; i < 2; i++) {
#pragma unroll
            for (int j = 0; j < 2; j++) {
                float x00 = ll1[2*i][2*j],     x01 = ll1[2*i][2*j+1];
                float x10 = ll1[2*i+1][2*j],   x11 = ll1[2*i+1][2*j+1];
                float s0 = x00 + x01, s1 = x10 + x11;
                float d0 = x01 - x00, d1 = x11 - x10;
                ll2[i][j] = (s0 + s1) * 0.5f;
                mx[3] = fmaxf(mx[3], fabsf((s1 - s0) * 0.5f));
                mx[4] = fmaxf(mx[4], fabsf((d0 + d1) * 0.5f));
                mx[5] = fmaxf(mx[5], fabsf((d1 - d0) * 0.5f));
            }
        }

        // Level 3 (single coefficient set per tile)
        {
            float x00 = ll2[0][0], x01 = ll2[0][1];
            float x10 = ll2[1][0], x11 = ll2[1][1];
            float s0 = x00 + x01, s1 = x10 + x11;
            float d0 = x01 - x00, d1 = x11 - x10;
            mx[6] = fabsf((s1 - s0) * 0.5f);
            mx[7] = fabsf((d0 + d1) * 0.5f);
            mx[8] = fabsf((d1 - d0) * 0.5f);
        }
    }

    // Block reduction: warp shuffle -> shared -> 9 atomics per block.
    __shared__ float sred[9][8];
    int wid = threadIdx.x >> 5;
    int lid = threadIdx.x & 31;
#pragma unroll
    for (int k = 0; k < 9; k++) {
        float v = warp_max(mx[k]);
        if (lid == 0) sred[k][wid] = v;
    }
    __syncthreads();
    if (threadIdx.x < 9) {
        float v = sred[threadIdx.x][0];
#pragma unroll
        for (int w = 1; w < 8; w++) v = fmaxf(v, sred[threadIdx.x][w]);
        atomicMax(&g_absmax[threadIdx.x], __float_as_int(v));
    }
}

// ---------------------------------------------------------------------------
// Pass 2: check gates. If all raw gates fire (expected), the speculative
// output is exact -> return. Otherwise recompute the gated reconstruction.
// ---------------------------------------------------------------------------
__global__ __launch_bounds__(256) void wt_pass2(const float* __restrict__ x,
                                                float* __restrict__ out,
                                                int total_tiles) {
    // Raw gate comparisons (identical semantics to reference: max|t| > thr).
    bool r1lh = __int_as_float(g_absmax[0]) > 0.25f;
    bool r1hl = __int_as_float(g_absmax[1]) > 0.25f;
    bool r1hh = __int_as_float(g_absmax[2]) > 0.25f;
    bool r2lh = __int_as_float(g_absmax[3]) > 0.5f;
    bool r2hl = __int_as_float(g_absmax[4]) > 0.5f;
    bool r2hh = __int_as_float(g_absmax[5]) > 0.5f;
    bool r3lh = __int_as_float(g_absmax[6]) > 1.0f;
    bool r3hl = __int_as_float(g_absmax[7]) > 1.0f;
    bool r3hh = __int_as_float(g_absmax[8]) > 1.0f;

    if (r1lh && r1hl && r1hh && r2lh && r2hl && r2hh && r3lh && r3hl && r3hh)
        return;  // fast path output from pass1 is exact

    // Effective (cascaded) gates
    float G3lh = r3lh ? 1.0f : 0.0f;
    float G3hl = r3hl ? 1.0f : 0.0f;
    float G3hh = r3hh ? 1.0f : 0.0f;
    float G2lh = (r2lh && r3lh) ? 1.0f : 0.0f;
    float G2hl = (r2hl && r3hl) ? 1.0f : 0.0f;
    float G2hh = (r2hh && r3hh) ? 1.0f : 0.0f;
    float G1lh = (r1lh && r2lh && r3lh) ? 1.0f : 0.0f;
    float G1hl = (r1hl && r2hl && r3hl) ? 1.0f : 0.0f;
    float G1hh = (r1hh && r2hh && r3hh) ? 1.0f : 0.0f;

    int t = blockIdx.x * 256 + threadIdx.x;
    if (t >= total_tiles) return;

    int tx = t % TX;
    int r  = t / TX;
    int ty = r % TY;
    int bc = r / TY;

    const float* xp = x + (size_t)bc * (HDIM * WDIM)
                        + (size_t)(ty * 8) * WDIM + tx * 8;

    float xv[8][8];
#pragma unroll
    for (int rr = 0; rr < 8; rr++) {
        float4 a = *reinterpret_cast<const float4*>(xp + rr * WDIM);
        float4 b = *reinterpret_cast<const float4*>(xp + rr * WDIM + 4);
        xv[rr][0] = a.x; xv[rr][1] = a.y; xv[rr][2] = a.z; xv[rr][3] = a.w;
        xv[rr][4] = b.x; xv[rr][5] = b.y; xv[rr][6] = b.z; xv[rr][7] = b.w;
    }

    // Level 1 LL only (H1 recomputed per-position at the end)
    float ll1[4][4];
#pragma unroll
    for (int i = 0; i < 4; i++) {
#pragma unroll
        for (int j = 0; j < 4; j++) {
            float x00 = xv[2*i][2*j],   x01 = xv[2*i][2*j+1];
            float x10 = xv[2*i+1][2*j], x11 = xv[2*i+1][2*j+1];
            ll1[i][j] = ((x00 + x01) + (x10 + x11)) * 0.5f;
        }
    }

    // Level 2 full
    float ll2[2][2], lh2[2][2], hl2[2][2], hh2[2][2];
#pragma unroll
    for (int i = 0; i < 2; i++) {
#pragma unroll
        for (int j = 0; j < 2; j++) {
            float x00 = ll1[2*i][2*j],   x01 = ll1[2*i][2*j+1];
            float x10 = ll1[2*i+1][2*j], x11 = ll1[2*i+1][2*j+1];
            float s0 = x00 + x01, s1 = x10 + x11;
            float d0 = x01 - x00, d1 = x11 - x10;
            ll2[i][j] = (s0 + s1) * 0.5f;
            lh2[i][j] = (s1 - s0) * 0.5f;
            hl2[i][j] = (d0 + d1) * 0.5f;
            hh2[i][j] = (d1 - d0) * 0.5f;
        }
    }

    // Level 3 full
    float ll3, lh3, hl3, hh3;
    {
        float x00 = ll2[0][0], x01 = ll2[0][1];
        float x10 = ll2[1][0], x11 = ll2[1][1];
        float s0 = x00 + x01, s1 = x10 + x11;
        float d0 = x01 - x00, d1 = x11 - x10;
        ll3 = (s0 + s1) * 0.5f;
        lh3 = (s1 - s0) * 0.5f;
        hl3 = (d0 + d1) * 0.5f;
        hh3 = (d1 - d0) * 0.5f;
    }

    // IDWT level3 -> r2 [2][2]
    float r2v[2][2];
    {
        float a = ll3, b = G3lh * lh3, c = G3hl * hl3, d = G3hh * hh3;
        r2v[0][0] = (a - b - c + d) * 0.5f;
        r2v[0][1] = (a - b + c - d) * 0.5f;
        r2v[1][0] = (a + b - c - d) * 0.5f;
        r2v[1][1] = (a + b + c + d) * 0.5f;
    }

    // IDWT level2 -> r1 [4][4]
    float r1v[4][4];
#pragma unroll
    for (int i = 0; i < 2; i++) {
#pragma unroll
        for (int j = 0; j < 2; j++) {
            float a = r2v[i][j];
            float b = G2lh * lh2[i][j];
            float c = G2hl * hl2[i][j];
            float d = G2hh * hh2[i][j];
            r1v[2*i][2*j]     = (a - b - c + d) * 0.5f;
            r1v[2*i][2*j+1]   = (a - b + c - d) * 0.5f;
            r1v[2*i+1][2*j]   = (a + b - c - d) * 0.5f;
            r1v[2*i+1][2*j+1] = (a + b + c + d) * 0.5f;
        }
    }

    // out = r1 + gated H1 (H1 recomputed from xv)
    float* op = out + (size_t)bc * (OH * OW)
                    + (size_t)(ty * 4) * OW + tx * 4;
#pragma unroll
    for (int i = 0; i < 4; i++) {
        float row[4];
#pragma unroll
        for (int j = 0; j < 4; j++) {
            float x00 = xv[2*i][2*j],   x01 = xv[2*i][2*j+1];
            float x10 = xv[2*i+1][2*j], x11 = xv[2*i+1][2*j+1];
            float s0 = x00 + x01, s1 = x10 + x11;
            float d0 = x01 - x00, d1 = x11 - x10;
            float lh1 = (s1 - s0) * 0.5f;
            float hl1 = (d0 + d1) * 0.5f;
            float hh1 = (d1 - d0) * 0.5f;
            row[j] = r1v[i][j] + G1lh * lh1 + G1hl * hl1 + G1hh * hh1;
        }
        float4 o; o.x = row[0]; o.y = row[1]; o.z = row[2]; o.w = row[3];
        *reinterpret_cast<float4*>(op + i * OW) = o;
    }
}

extern "C" void kernel_launch(void* const* d_in, const int* in_sizes, int n_in,
                              void* d_out, int out_size) {
    const float* x = (const float*)d_in[0];
    float* out = (float*)d_out;

    int n  = in_sizes[0];
    int bc = n / (HDIM * WDIM);          // B*C planes
    int total_tiles = bc * TPB;          // 1,204,224 for the bench shape
    int blocks = (total_tiles + 255) / 256;

    wt_init<<<1, 32>>>();
    wt_pass1<<<blocks, 256>>>(x, out, total_tiles);
    wt_pass2<<<blocks, 256>>>(x, out, total_tiles);
}

// round 2
// speedup vs baseline: 1.3056x; 1.3056x over previous
#include <cuda_runtime.h>

// WaveletTree: 3-level gated Haar DWT/IDWT tree.
// x: [B,C,224,224] f32 -> out: [B,C,112,112] f32.
// Gate = (max|subband| > thr) is an existence test: a cheap probe over a
// sparse tile subset can CONFIRM gates without a full scan. If all 9 gates
// are confirmed, out = 2*x[:,:,1::2,1::2] exactly (idwt(dwt)=id telescopes),
// needing only the odd input rows (half the read traffic).

namespace {
constexpr int HDIM = 224;
constexpr int WDIM = 224;
constexpr int OH   = 112;
constexpr int OW   = 112;
constexpr int TX   = 28;       // tiles per row (224/8)
constexpr int TY   = 28;
constexpr int TPB  = TX * TY;  // tiles per (b,c) plane
constexpr int PROBE_THREADS = 8192;   // tiles probed
constexpr unsigned ALL_CONF = 0x1FFu; // 9 gates
}

// order: [lh1, hl1, hh1, lh2, hl2, hh2, lh3, hl3, hh3]
__device__ int g_absmax[9];        // float bits as int (non-negative floats)
__device__ unsigned g_conf;        // bit k: gate k confirmed > thr by probe

__global__ void wt_init() {
    if (threadIdx.x < 9) g_absmax[threadIdx.x] = 0;
    if (threadIdx.x == 9) g_conf = 0u;
}

__device__ __forceinline__ float warp_max(float v) {
#pragma unroll
    for (int o = 16; o; o >>= 1)
        v = fmaxf(v, __shfl_xor_sync(0xffffffffu, v, o));
    return v;
}

// Compute the 9 per-tile subband abs-maxes from an 8x8 tile in registers.
__device__ __forceinline__ void tile_submax(const float xv[8][8], float mx[9]) {
    float ll1[4][4];
#pragma unroll
    for (int i = 0; i < 4; i++) {
#pragma unroll
        for (int j = 0; j < 4; j++) {
            float x00 = xv[2*i][2*j],   x01 = xv[2*i][2*j+1];
            float x10 = xv[2*i+1][2*j], x11 = xv[2*i+1][2*j+1];
            float s0 = x00 + x01, s1 = x10 + x11;
            float d0 = x01 - x00, d1 = x11 - x10;
            ll1[i][j] = (s0 + s1) * 0.5f;
            mx[0] = fmaxf(mx[0], fabsf((s1 - s0) * 0.5f));
            mx[1] = fmaxf(mx[1], fabsf((d0 + d1) * 0.5f));
            mx[2] = fmaxf(mx[2], fabsf((d1 - d0) * 0.5f));
        }
    }
    float ll2[2][2];
#pragma unroll
    for (int i = 0; i < 2; i++) {
#pragma unroll
        for (int j = 0; j < 2; j++) {
            float x00 = ll1[2*i][2*j],   x01 = ll1[2*i][2*j+1];
            float x10 = ll1[2*i+1][2*j], x11 = ll1[2*i+1][2*j+1];
            float s0 = x00 + x01, s1 = x10 + x11;
            float d0 = x01 - x00, d1 = x11 - x10;
            ll2[i][j] = (s0 + s1) * 0.5f;
            mx[3] = fmaxf(mx[3], fabsf((s1 - s0) * 0.5f));
            mx[4] = fmaxf(mx[4], fabsf((d0 + d1) * 0.5f));
            mx[5] = fmaxf(mx[5], fabsf((d1 - d0) * 0.5f));
        }
    }
    {
        float x00 = ll2[0][0], x01 = ll2[0][1];
        float x10 = ll2[1][0], x11 = ll2[1][1];
        float s0 = x00 + x01, s1 = x10 + x11;
        float d0 = x01 - x00, d1 = x11 - x10;
        mx[6] = fmaxf(mx[6], fabsf((s1 - s0) * 0.5f));
        mx[7] = fmaxf(mx[7], fabsf((d0 + d1) * 0.5f));
        mx[8] = fmaxf(mx[8], fabsf((d1 - d0) * 0.5f));
    }
}

__device__ __forceinline__ void load_tile(const float* __restrict__ xp,
                                          float xv[8][8]) {
#pragma unroll
    for (int rr = 0; rr < 8; rr++) {
        float4 a = *reinterpret_cast<const float4*>(xp + rr * WDIM);
        float4 b = *reinterpret_cast<const float4*>(xp + rr * WDIM + 4);
        xv[rr][0] = a.x; xv[rr][1] = a.y; xv[rr][2] = a.z; xv[rr][3] = a.w;
        xv[rr][4] = b.x; xv[rr][5] = b.y; xv[rr][6] = b.z; xv[rr][7] = b.w;
    }
}

// ---------------------------------------------------------------------------
// Probe: sparse strided tile subset; confirm gates via atomicOr.
// ---------------------------------------------------------------------------
__global__ __launch_bounds__(256) void wt_probe(const float* __restrict__ x,
                                                int total_tiles, int stride) {
    int p = blockIdx.x * 256 + threadIdx.x;
    long long tt = (long long)p * stride;
    unsigned mask = 0;
    if (tt < total_tiles) {
        int t  = (int)tt;
        int tx = t % TX;
        int r  = t / TX;
        int ty = r % TY;
        int bc = r / TY;
        const float* xp = x + (size_t)bc * (HDIM * WDIM)
                            + (size_t)(ty * 8) * WDIM + tx * 8;
        float xv[8][8];
        load_tile(xp, xv);
        float mx[9];
#pragma unroll
        for (int k = 0; k < 9; k++) mx[k] = 0.0f;
        tile_submax(xv, mx);
        const float thr[9] = {0.25f, 0.25f, 0.25f, 0.5f, 0.5f, 0.5f, 1.0f, 1.0f, 1.0f};
#pragma unroll
        for (int k = 0; k < 9; k++)
            if (mx[k] > thr[k]) mask |= (1u << k);
    }
    // warp OR then one atomic per warp
#pragma unroll
    for (int o = 16; o; o >>= 1)
        mask |= __shfl_xor_sync(0xffffffffu, mask, o);
    if ((threadIdx.x & 31) == 0 && mask)
        atomicOr(&g_conf, mask);
}

// ---------------------------------------------------------------------------
// Main: fast path (all gates confirmed) reads only odd rows + writes 2*x11.
// Slow path: full scan, absmax reduction, speculative write.
// ---------------------------------------------------------------------------
__global__ __launch_bounds__(256, 2) void wt_main(const float* __restrict__ x,
                                                  float* __restrict__ out,
                                                  int total_tiles) {
    bool fast = (g_conf == ALL_CONF);
    int t = blockIdx.x * 256 + threadIdx.x;

    if (fast) {
        if (t >= total_tiles) return;
        int tx = t % TX;
        int r  = t / TX;
        int ty = r % TY;
        int bc = r / TY;
        const float* xp = x + (size_t)bc * (HDIM * WDIM)
                            + (size_t)(ty * 8) * WDIM + tx * 8;
        float* op = out + (size_t)bc * (OH * OW)
                        + (size_t)(ty * 4) * OW + tx * 4;
#pragma unroll
        for (int rr = 0; rr < 4; rr++) {
            const float* rp = xp + (size_t)(2 * rr + 1) * WDIM;
            float4 a = *reinterpret_cast<const float4*>(rp);
            float4 b = *reinterpret_cast<const float4*>(rp + 4);
            float4 o;
            o.x = 2.0f * a.y;
            o.y = 2.0f * a.w;
            o.z = 2.0f * b.y;
            o.w = 2.0f * b.w;
            *reinterpret_cast<float4*>(op + rr * OW) = o;
        }
        return;
    }

    // ---- slow path: exact global abs-max + speculative write ----
    float mx[9];
#pragma unroll
    for (int k = 0; k < 9; k++) mx[k] = 0.0f;

    if (t < total_tiles) {
        int tx = t % TX;
        int r  = t / TX;
        int ty = r % TY;
        int bc = r / TY;
        const float* xp = x + (size_t)bc * (HDIM * WDIM)
                            + (size_t)(ty * 8) * WDIM + tx * 8;
        float xv[8][8];
        load_tile(xp, xv);

        // speculative fast-path output (exact if all raw gates end up true)
        float* op = out + (size_t)bc * (OH * OW)
                        + (size_t)(ty * 4) * OW + tx * 4;
#pragma unroll
        for (int rr = 0; rr < 4; rr++) {
            float4 o;
            o.x = 2.0f * xv[2*rr+1][1];
            o.y = 2.0f * xv[2*rr+1][3];
            o.z = 2.0f * xv[2*rr+1][5];
            o.w = 2.0f * xv[2*rr+1][7];
            *reinterpret_cast<float4*>(op + rr * OW) = o;
        }
        tile_submax(xv, mx);
    }

    __shared__ float sred[9][8];
    int wid = threadIdx.x >> 5;
    int lid = threadIdx.x & 31;
#pragma unroll
    for (int k = 0; k < 9; k++) {
        float v = warp_max(mx[k]);
        if (lid == 0) sred[k][wid] = v;
    }
    __syncthreads();
    if (threadIdx.x < 9) {
        float v = sred[threadIdx.x][0];
#pragma unroll
        for (int w = 1; w < 8; w++) v = fmaxf(v, sred[threadIdx.x][w]);
        atomicMax(&g_absmax[threadIdx.x], __float_as_int(v));
    }
}

// ---------------------------------------------------------------------------
// Pass 2: no-op on confirmed fast path. Else: gates from exact absmax;
// if all raw gates true the speculative write stands; otherwise reconstruct.
// ---------------------------------------------------------------------------
__global__ __launch_bounds__(256) void wt_pass2(const float* __restrict__ x,
                                                float* __restrict__ out,
                                                int total_tiles) {
    if (g_conf == ALL_CONF) return;

    bool r1lh = __int_as_float(g_absmax[0]) > 0.25f;
    bool r1hl = __int_as_float(g_absmax[1]) > 0.25f;
    bool r1hh = __int_as_float(g_absmax[2]) > 0.25f;
    bool r2lh = __int_as_float(g_absmax[3]) > 0.5f;
    bool r2hl = __int_as_float(g_absmax[4]) > 0.5f;
    bool r2hh = __int_as_float(g_absmax[5]) > 0.5f;
    bool r3lh = __int_as_float(g_absmax[6]) > 1.0f;
    bool r3hl = __int_as_float(g_absmax[7]) > 1.0f;
    bool r3hh = __int_as_float(g_absmax[8]) > 1.0f;

    if (r1lh && r1hl && r1hh && r2lh && r2hl && r2hh && r3lh && r3hl && r3hh)
        return;  // speculative write from wt_main slow path is exact

    float G3lh = r3lh ? 1.0f : 0.0f;
    float G3hl = r3hl ? 1.0f : 0.0f;
    float G3hh = r3hh ? 1.0f : 0.0f;
    float G2lh = (r2lh && r3lh) ? 1.0f : 0.0f;
    float G2hl = (r2hl && r3hl) ? 1.0f : 0.0f;
    float G2hh = (r2hh && r3hh) ? 1.0f : 0.0f;
    float G1lh = (r1lh && r2lh && r3lh) ? 1.0f : 0.0f;
    float G1hl = (r1hl && r2hl && r3hl) ? 1.0f : 0.0f;
    float G1hh = (r1hh && r2hh && r3hh) ? 1.0f : 0.0f;

    int t = blockIdx.x * 256 + threadIdx.x;
    if (t >= total_tiles) return;

    int tx = t % TX;
    int r  = t / TX;
    int ty = r % TY;
    int bc = r / TY;

    const float* xp = x + (size_t)bc * (HDIM * WDIM)
                        + (size_t)(ty * 8) * WDIM + tx * 8;
    float xv[8][8];
    load_tile(xp, xv);

    float ll1[4][4];
#pragma unroll
    for (int i = 0; i < 4; i++) {
#pragma unroll
        for (int j = 0; j < 4; j++) {
            float x00 = xv[2*i][2*j],   x01 = xv[2*i][2*j+1];
            float x10 = xv[2*i+1][2*j], x11 = xv[2*i+1][2*j+1];
            ll1[i][j] = ((x00 + x01) + (x10 + x11)) * 0.5f;
        }
    }

    float ll2[2][2], lh2[2][2], hl2[2][2], hh2[2][2];
#pragma unroll
    for (int i = 0; i < 2; i++) {
#pragma unroll
        for (int j = 0; j < 2; j++) {
            float x00 = ll1[2*i][2*j],   x01 = ll1[2*i][2*j+1];
            float x10 = ll1[2*i+1][2*j], x11 = ll1[2*i+1][2*j+1];
            float s0 = x00 + x01, s1 = x10 + x11;
            float d0 = x01 - x00, d1 = x11 - x10;
            ll2[i][j] = (s0 + s1) * 0.5f;
            lh2[i][j] = (s1 - s0) * 0.5f;
            hl2[i][j] = (d0 + d1) * 0.5f;
            hh2[i][j] = (d1 - d0) * 0.5f;
        }
    }

    float ll3, lh3, hl3, hh3;
    {
        float x00 = ll2[0][0], x01 = ll2[0][1];
        float x10 = ll2[1][0], x11 = ll2[1][1];
        float s0 = x00 + x01, s1 = x10 + x11;
        float d0 = x01 - x00, d1 = x11 - x10;
        ll3 = (s0 + s1) * 0.5f;
        lh3 = (s1 - s0) * 0.5f;
        hl3 = (d0 + d1) * 0.5f;
        hh3 = (d1 - d0) * 0.5f;
    }

    float r2v[2][2];
    {
        float a = ll3, b = G3lh * lh3, c = G3hl * hl3, d = G3hh * hh3;
        r2v[0][0] = (a - b - c + d) * 0.5f;
        r2v[0][1] = (a - b + c - d) * 0.5f;
        r2v[1][0] = (a + b - c - d) * 0.5f;
        r2v[1][1] = (a + b + c + d) * 0.5f;
    }

    float r1v[4][4];
#pragma unroll
    for (int i = 0; i < 2; i++) {
#pragma unroll
        for (int j = 0; j < 2; j++) {
            float a = r2v[i][j];
            float b = G2lh * lh2[i][j];
            float c = G2hl * hl2[i][j];
            float d = G2hh * hh2[i][j];
            r1v[2*i][2*j]     = (a - b - c + d) * 0.5f;
            r1v[2*i][2*j+1]   = (a - b + c - d) * 0.5f;
            r1v[2*i+1][2*j]   = (a + b - c - d) * 0.5f;
            r1v[2*i+1][2*j+1] = (a + b + c + d) * 0.5f;
        }
    }

    float* op = out + (size_t)bc * (OH * OW)
                    + (size_t)(ty * 4) * OW + tx * 4;
#pragma unroll
    for (int i = 0; i < 4; i++) {
        float row[4];
#pragma unroll
        for (int j = 0; j < 4; j++) {
            float x00 = xv[2*i][2*j],   x01 = xv[2*i][2*j+1];
            float x10 = xv[2*i+1][2*j], x11 = xv[2*i+1][2*j+1];
            float s0 = x00 + x01, s1 = x10 + x11;
            float d0 = x01 - x00, d1 = x11 - x10;
            float lh1 = (s1 - s0) * 0.5f;
            float hl1 = (d0 + d1) * 0.5f;
            float hh1 = (d1 - d0) * 0.5f;
            row[j] = r1v[i][j] + G1lh * lh1 + G1hl * hl1 + G1hh * hh1;
        }
        float4 o; o.x = row[0]; o.y = row[1]; o.z = row[2]; o.w = row[3];
        *reinterpret_cast<float4*>(op + i * OW) = o;
    }
}

extern "C" void kernel_launch(void* const* d_in, const int* in_sizes, int n_in,
                              void* d_out, int out_size) {
    const float* x = (const float*)d_in[0];
    float* out = (float*)d_out;

    int n  = in_sizes[0];
    int bc = n / (HDIM * WDIM);          // B*C planes
    int total_tiles = bc * TPB;
    int blocks = (total_tiles + 255) / 256;

    int stride = total_tiles / PROBE_THREADS;
    if (stride < 1) stride = 1;

    wt_init<<<1, 32>>>();
    wt_probe<<<PROBE_THREADS / 256, 256>>>(x, total_tiles, stride);
    wt_main<<<blocks, 256>>>(x, out, total_tiles);
    wt_pass2<<<blocks, 256>>>(x, out, total_tiles);
}

// round 3
// speedup vs baseline: 1.3623x; 1.0434x over previous
#include <cuda_runtime.h>

// WaveletTree: 3-level gated Haar DWT/IDWT tree.
// x: [B,C,224,224] f32 -> out: [B,C,112,112] f32.
// Gate = (max|subband| > thr) is an existence test: a sparse probe can CONFIRM
// gates without a full scan. With all 9 gates confirmed, idwt(dwt) telescopes:
// out = 2*x[:,:,1::2,1::2] exactly, needing only odd input rows (half read).
// All device-global state uses overwrite semantics (no init kernel needed
// across graph replays), except g_absmax which is zeroed by a spare probe block.

namespace {
constexpr int HDIM = 224;
constexpr int WDIM = 224;
constexpr int OH   = 112;
constexpr int OW   = 112;
constexpr int TX   = 28;       // tiles per row (224/8)
constexpr int TY   = 28;
constexpr int TPB  = TX * TY;  // tiles per (b,c) plane
constexpr int PROBE_BLOCKS  = 32;
constexpr int PROBE_THREADS = PROBE_BLOCKS * 256;  // 8192 tiles probed
constexpr unsigned ALL_CONF = 0x1FFu;              // 9 gates
constexpr int P2_BLOCKS = 1184;                    // grid-stride pass2
}

// order: [lh1, hl1, hh1, lh2, hl2, hh2, lh3, hl3, hh3]
__device__ int g_absmax[9];              // float bits as int (non-neg floats)
__device__ unsigned g_probe[PROBE_BLOCKS];  // per-block confirm masks (overwritten)

__device__ __forceinline__ float warp_max(float v) {
#pragma unroll
    for (int o = 16; o; o >>= 1)
        v = fmaxf(v, __shfl_xor_sync(0xffffffffu, v, o));
    return v;
}

__device__ __forceinline__ unsigned warp_or(unsigned m) {
#pragma unroll
    for (int o = 16; o; o >>= 1)
        m |= __shfl_xor_sync(0xffffffffu, m, o);
    return m;
}

// Combined probe mask, computed per-block from the 32 slots (L2 hits).
__device__ __forceinline__ bool conf_all(unsigned* sconf_shared) {
    if (threadIdx.x < 32) {
        unsigned m = g_probe[threadIdx.x];
        m = warp_or(m);
        if (threadIdx.x == 0) *sconf_shared = m;
    }
    __syncthreads();
    return (*sconf_shared == ALL_CONF);
}

__device__ __forceinline__ void load_tile(const float* __restrict__ xp,
                                          float xv[8][8]) {
#pragma unroll
    for (int rr = 0; rr < 8; rr++) {
        float4 a = *reinterpret_cast<const float4*>(xp + rr * WDIM);
        float4 b = *reinterpret_cast<const float4*>(xp + rr * WDIM + 4);
        xv[rr][0] = a.x; xv[rr][1] = a.y; xv[rr][2] = a.z; xv[rr][3] = a.w;
        xv[rr][4] = b.x; xv[rr][5] = b.y; xv[rr][6] = b.z; xv[rr][7] = b.w;
    }
}

// 9 per-tile subband abs-maxes from an 8x8 tile in registers.
__device__ __forceinline__ void tile_submax(const float xv[8][8], float mx[9]) {
    float ll1[4][4];
#pragma unroll
    for (int i = 0; i < 4; i++) {
#pragma unroll
        for (int j = 0; j < 4; j++) {
            float x00 = xv[2*i][2*j],   x01 = xv[2*i][2*j+1];
            float x10 = xv[2*i+1][2*j], x11 = xv[2*i+1][2*j+1];
            float s0 = x00 + x01, s1 = x10 + x11;
            float d0 = x01 - x00, d1 = x11 - x10;
            ll1[i][j] = (s0 + s1) * 0.5f;
            mx[0] = fmaxf(mx[0], fabsf((s1 - s0) * 0.5f));
            mx[1] = fmaxf(mx[1], fabsf((d0 + d1) * 0.5f));
            mx[2] = fmaxf(mx[2], fabsf((d1 - d0) * 0.5f));
        }
    }
    float ll2[2][2];
#pragma unroll
    for (int i = 0; i < 2; i++) {
#pragma unroll
        for (int j = 0; j < 2; j++) {
            float x00 = ll1[2*i][2*j],   x01 = ll1[2*i][2*j+1];
            float x10 = ll1[2*i+1][2*j], x11 = ll1[2*i+1][2*j+1];
            float s0 = x00 + x01, s1 = x10 + x11;
            float d0 = x01 - x00, d1 = x11 - x10;
            ll2[i][j] = (s0 + s1) * 0.5f;
            mx[3] = fmaxf(mx[3], fabsf((s1 - s0) * 0.5f));
            mx[4] = fmaxf(mx[4], fabsf((d0 + d1) * 0.5f));
            mx[5] = fmaxf(mx[5], fabsf((d1 - d0) * 0.5f));
        }
    }
    {
        float x00 = ll2[0][0], x01 = ll2[0][1];
        float x10 = ll2[1][0], x11 = ll2[1][1];
        float s0 = x00 + x01, s1 = x10 + x11;
        float d0 = x01 - x00, d1 = x11 - x10;
        mx[6] = fmaxf(mx[6], fabsf((s1 - s0) * 0.5f));
        mx[7] = fmaxf(mx[7], fabsf((d0 + d1) * 0.5f));
        mx[8] = fmaxf(mx[8], fabsf((d1 - d0) * 0.5f));
    }
}

// ---------------------------------------------------------------------------
// Probe (33 blocks): blocks 0..31 probe strided tiles, block 32 zeroes absmax.
// Slots are plain-stored -> no init kernel needed across graph replays.
// ---------------------------------------------------------------------------
__global__ __launch_bounds__(256) void wt_probe(const float* __restrict__ x,
                                                int total_tiles, int stride) {
    if (blockIdx.x == PROBE_BLOCKS) {
        if (threadIdx.x < 9) g_absmax[threadIdx.x] = 0;
        return;
    }
    int p = blockIdx.x * 256 + threadIdx.x;
    long long tt = (long long)p * stride;
    unsigned mask = 0;
    if (tt < total_tiles) {
        int t  = (int)tt;
        int tx = t % TX;
        int r  = t / TX;
        int ty = r % TY;
        int bc = r / TY;
        const float* xp = x + (size_t)bc * (HDIM * WDIM)
                            + (size_t)(ty * 8) * WDIM + tx * 8;
        float xv[8][8];
        load_tile(xp, xv);
        float mx[9];
#pragma unroll
        for (int k = 0; k < 9; k++) mx[k] = 0.0f;
        tile_submax(xv, mx);
        const float thr[9] = {0.25f, 0.25f, 0.25f, 0.5f, 0.5f, 0.5f, 1.0f, 1.0f, 1.0f};
#pragma unroll
        for (int k = 0; k < 9; k++)
            if (mx[k] > thr[k]) mask |= (1u << k);
    }
    __shared__ unsigned swor[8];
    mask = warp_or(mask);
    int wid = threadIdx.x >> 5;
    if ((threadIdx.x & 31) == 0) swor[wid] = mask;
    __syncthreads();
    if (threadIdx.x == 0) {
        unsigned m = swor[0];
#pragma unroll
        for (int w = 1; w < 8; w++) m |= swor[w];
        g_probe[blockIdx.x] = m;   // overwrite: deterministic per launch
    }
}

// ---------------------------------------------------------------------------
// Main: fast path (all gates confirmed) reads only odd rows, writes 2*x11.
// Slow path: full scan, absmax reduction, speculative write.
// ---------------------------------------------------------------------------
__global__ __launch_bounds__(256, 2) void wt_main(const float* __restrict__ x,
                                                  float* __restrict__ out,
                                                  int total_tiles) {
    __shared__ unsigned sconf;
    bool fast = conf_all(&sconf);
    int t = blockIdx.x * 256 + threadIdx.x;

    if (fast) {
        if (t >= total_tiles) return;
        int tx = t % TX;
        int r  = t / TX;
        int ty = r % TY;
        int bc = r / TY;
        const float* xp = x + (size_t)bc * (HDIM * WDIM)
                            + (size_t)(ty * 8) * WDIM + tx * 8;
        float* op = out + (size_t)bc * (OH * OW)
                        + (size_t)(ty * 4) * OW + tx * 4;
#pragma unroll
        for (int rr = 0; rr < 4; rr++) {
            const float* rp = xp + (size_t)(2 * rr + 1) * WDIM;
            float4 a = *reinterpret_cast<const float4*>(rp);
            float4 b = *reinterpret_cast<const float4*>(rp + 4);
            float4 o;
            o.x = 2.0f * a.y;
            o.y = 2.0f * a.w;
            o.z = 2.0f * b.y;
            o.w = 2.0f * b.w;
            *reinterpret_cast<float4*>(op + rr * OW) = o;
        }
        return;
    }

    // ---- slow path: exact global abs-max + speculative write ----
    float mx[9];
#pragma unroll
    for (int k = 0; k < 9; k++) mx[k] = 0.0f;

    if (t < total_tiles) {
        int tx = t % TX;
        int r  = t / TX;
        int ty = r % TY;
        int bc = r / TY;
        const float* xp = x + (size_t)bc * (HDIM * WDIM)
                            + (size_t)(ty * 8) * WDIM + tx * 8;
        float xv[8][8];
        load_tile(xp, xv);

        float* op = out + (size_t)bc * (OH * OW)
                        + (size_t)(ty * 4) * OW + tx * 4;
#pragma unroll
        for (int rr = 0; rr < 4; rr++) {
            float4 o;
            o.x = 2.0f * xv[2*rr+1][1];
            o.y = 2.0f * xv[2*rr+1][3];
            o.z = 2.0f * xv[2*rr+1][5];
            o.w = 2.0f * xv[2*rr+1][7];
            *reinterpret_cast<float4*>(op + rr * OW) = o;
        }
        tile_submax(xv, mx);
    }

    __shared__ float sred[9][8];
    int wid = threadIdx.x >> 5;
    int lid = threadIdx.x & 31;
#pragma unroll
    for (int k = 0; k < 9; k++) {
        float v = warp_max(mx[k]);
        if (lid == 0) sred[k][wid] = v;
    }
    __syncthreads();
    if (threadIdx.x < 9) {
        float v = sred[threadIdx.x][0];
#pragma unroll
        for (int w = 1; w < 8; w++) v = fmaxf(v, sred[threadIdx.x][w]);
        atomicMax(&g_absmax[threadIdx.x], __float_as_int(v));
    }
}

// ---------------------------------------------------------------------------
// Pass 2 (grid-stride, small grid): no-op on confirmed fast path. Else gates
// from exact absmax; if all raw gates true the speculative write stands;
// otherwise reconstruct exactly.
// ---------------------------------------------------------------------------
__global__ __launch_bounds__(256) void wt_pass2(const float* __restrict__ x,
                                                float* __restrict__ out,
                                                int total_tiles) {
    __shared__ unsigned sconf;
    if (conf_all(&sconf)) return;

    bool r1lh = __int_as_float(g_absmax[0]) > 0.25f;
    bool r1hl = __int_as_float(g_absmax[1]) > 0.25f;
    bool r1hh = __int_as_float(g_absmax[2]) > 0.25f;
    bool r2lh = __int_as_float(g_absmax[3]) > 0.5f;
    bool r2hl = __int_as_float(g_absmax[4]) > 0.5f;
    bool r2hh = __int_as_float(g_absmax[5]) > 0.5f;
    bool r3lh = __int_as_float(g_absmax[6]) > 1.0f;
    bool r3hl = __int_as_float(g_absmax[7]) > 1.0f;
    bool r3hh = __int_as_float(g_absmax[8]) > 1.0f;

    if (r1lh && r1hl && r1hh && r2lh && r2hl && r2hh && r3lh && r3hl && r3hh)
        return;  // speculative write from wt_main slow path is exact

    float G3lh = r3lh ? 1.0f : 0.0f;
    float G3hl = r3hl ? 1.0f : 0.0f;
    float G3hh = r3hh ? 1.0f : 0.0f;
    float G2lh = (r2lh && r3lh) ? 1.0f : 0.0f;
    float G2hl = (r2hl && r3hl) ? 1.0f : 0.0f;
    float G2hh = (r2hh && r3hh) ? 1.0f : 0.0f;
    float G1lh = (r1lh && r2lh && r3lh) ? 1.0f : 0.0f;
    float G1hl = (r1hl && r2hl && r3hl) ? 1.0f : 0.0f;
    float G1hh = (r1hh && r2hh && r3hh) ? 1.0f : 0.0f;

    for (int t = blockIdx.x * 256 + threadIdx.x; t < total_tiles;
         t += gridDim.x * 256) {
        int tx = t % TX;
        int r  = t / TX;
        int ty = r % TY;
        int bc = r / TY;

        const float* xp = x + (size_t)bc * (HDIM * WDIM)
                            + (size_t)(ty * 8) * WDIM + tx * 8;
        float xv[8][8];
        load_tile(xp, xv);

        float ll1[4][4];
#pragma unroll
        for (int i = 0; i < 4; i++) {
#pragma unroll
            for (int j = 0; j < 4; j++) {
                float x00 = xv[2*i][2*j],   x01 = xv[2*i][2*j+1];
                float x10 = xv[2*i+1][2*j], x11 = xv[2*i+1][2*j+1];
                ll1[i][j] = ((x00 + x01) + (x10 + x11)) * 0.5f;
            }
        }

        float ll2[2][2], lh2[2][2], hl2[2][2], hh2[2][2];
#pragma unroll
        for (int i = 0; i < 2; i++) {
#pragma unroll
            for (int j = 0; j < 2; j++) {
                float x00 = ll1[2*i][2*j],   x01 = ll1[2*i][2*j+1];
                float x10 = ll1[2*i+1][2*j], x11 = ll1[2*i+1][2*j+1];
                float s0 = x00 + x01, s1 = x10 + x11;
                float d0 = x01 - x00, d1 = x11 - x10;
                ll2[i][j] = (s0 + s1) * 0.5f;
                lh2[i][j] = (s1 - s0) * 0.5f;
                hl2[i][j] = (d0 + d1) * 0.5f;
                hh2[i][j] = (d1 - d0) * 0.5f;
            }
        }

        float ll3, lh3, hl3, hh3;
        {
            float x00 = ll2[0][0], x01 = ll2[0][1];
            float x10 = ll2[1][0], x11 = ll2[1][1];
            float s0 = x00 + x01, s1 = x10 + x11;
            float d0 = x01 - x00, d1 = x11 - x10;
            ll3 = (s0 + s1) * 0.5f;
            lh3 = (s1 - s0) * 0.5f;
            hl3 = (d0 + d1) * 0.5f;
            hh3 = (d1 - d0) * 0.5f;
        }

        float r2v[2][2];
        {
            float a = ll3, b = G3lh * lh3, c = G3hl * hl3, d = G3hh * hh3;
            r2v[0][0] = (a - b - c + d) * 0.5f;
            r2v[0][1] = (a - b + c - d) * 0.5f;
            r2v[1][0] = (a + b - c - d) * 0.5f;
            r2v[1][1] = (a + b + c + d) * 0.5f;
        }

        float r1v[4][4];
#pragma unroll
        for (int i = 0; i < 2; i++) {
#pragma unroll
            for (int j = 0; j < 2; j++) {
                float a = r2v[i][j];
                float b = G2lh * lh2[i][j];
                float c = G2hl * hl2[i][j];
                float d = G2hh * hh2[i][j];
                r1v[2*i][2*j]     = (a - b - c + d) * 0.5f;
                r1v[2*i][2*j+1]   = (a - b + c - d) * 0.5f;
                r1v[2*i+1][2*j]   = (a + b - c - d) * 0.5f;
                r1v[2*i+1][2*j+1] = (a + b + c + d) * 0.5f;
            }
        }

        float* op = out + (size_t)bc * (OH * OW)
                        + (size_t)(ty * 4) * OW + tx * 4;
#pragma unroll
        for (int i = 0; i < 4; i++) {
            float row[4];
#pragma unroll
            for (int j = 0; j < 4; j++) {
                float x00 = xv[2*i][2*j],   x01 = xv[2*i][2*j+1];
                float x10 = xv[2*i+1][2*j], x11 = xv[2*i+1][2*j+1];
                float s0 = x00 + x01, s1 = x10 + x11;
                float d0 = x01 - x00, d1 = x11 - x10;
                float lh1 = (s1 - s0) * 0.5f;
                float hl1 = (d0 + d1) * 0.5f;
                float hh1 = (d1 - d0) * 0.5f;
                row[j] = r1v[i][j] + G1lh * lh1 + G1hl * hl1 + G1hh * hh1;
            }
            float4 o; o.x = row[0]; o.y = row[1]; o.z = row[2]; o.w = row[3];
            *reinterpret_cast<float4*>(op + i * OW) = o;
        }
    }
}

extern "C" void kernel_launch(void* const* d_in, const int* in_sizes, int n_in,
                              void* d_out, int out_size) {
    const float* x = (const float*)d_in[0];
    float* out = (float*)d_out;

    int n  = in_sizes[0];
    int bc = n / (HDIM * WDIM);          // B*C planes
    int total_tiles = bc * TPB;
    int blocks = (total_tiles + 255) / 256;

    int stride = total_tiles / PROBE_THREADS;
    if (stride < 1) stride = 1;

    wt_probe<<<PROBE_BLOCKS + 1, 256>>>(x, total_tiles, stride);
    wt_main<<<blocks, 256>>>(x, out, total_tiles);
    wt_pass2<<<P2_BLOCKS, 256>>>(x, out, total_tiles);
}

// round 4
// speedup vs baseline: 1.4111x; 1.0358x over previous
#include <cuda_runtime.h>

// WaveletTree: 3-level gated Haar DWT/IDWT tree.
// x: [B,C,224,224] f32 -> out: [B,C,112,112] f32.
// Gate = (max|subband| > thr) is an existence test: a sparse probe can CONFIRM
// gates without a full scan. With all 9 gates confirmed, idwt(dwt) telescopes:
// out = 2*x[:,:,1::2,1::2] exactly, needing only odd input rows (half read).
// Probe reads 32 chunks of 256 CONSECUTIVE tiles (coalesced warp loads),
// spread across the tensor. Device-global state uses overwrite semantics.

namespace {
constexpr int HDIM = 224;
constexpr int WDIM = 224;
constexpr int OH   = 112;
constexpr int OW   = 112;
constexpr int TX   = 28;       // tiles per row (224/8)
constexpr int TY   = 28;
constexpr int TPB  = TX * TY;  // tiles per (b,c) plane
constexpr int PROBE_BLOCKS  = 32;
constexpr unsigned ALL_CONF = 0x1FFu;  // 9 gates
constexpr int P2_BLOCKS = 1184;        // grid-stride pass2
}

// order: [lh1, hl1, hh1, lh2, hl2, hh2, lh3, hl3, hh3]
__device__ int g_absmax[9];                 // float bits as int (non-neg)
__device__ unsigned g_probe[PROBE_BLOCKS];  // per-block masks (overwritten)

__device__ __forceinline__ float warp_max(float v) {
#pragma unroll
    for (int o = 16; o; o >>= 1)
        v = fmaxf(v, __shfl_xor_sync(0xffffffffu, v, o));
    return v;
}

__device__ __forceinline__ unsigned warp_or(unsigned m) {
#pragma unroll
    for (int o = 16; o; o >>= 1)
        m |= __shfl_xor_sync(0xffffffffu, m, o);
    return m;
}

// Combined probe mask from the 32 slots (L2 hits).
__device__ __forceinline__ bool conf_all(unsigned* sconf_shared) {
    if (threadIdx.x < 32) {
        unsigned m = g_probe[threadIdx.x];
        m = warp_or(m);
        if (threadIdx.x == 0) *sconf_shared = m;
    }
    __syncthreads();
    return (*sconf_shared == ALL_CONF);
}

__device__ __forceinline__ void load_tile(const float* __restrict__ xp,
                                          float xv[8][8]) {
#pragma unroll
    for (int rr = 0; rr < 8; rr++) {
        float4 a = *reinterpret_cast<const float4*>(xp + rr * WDIM);
        float4 b = *reinterpret_cast<const float4*>(xp + rr * WDIM + 4);
        xv[rr][0] = a.x; xv[rr][1] = a.y; xv[rr][2] = a.z; xv[rr][3] = a.w;
        xv[rr][4] = b.x; xv[rr][5] = b.y; xv[rr][6] = b.z; xv[rr][7] = b.w;
    }
}

// 9 per-tile subband abs-maxes from an 8x8 tile in registers.
__device__ __forceinline__ void tile_submax(const float xv[8][8], float mx[9]) {
    float ll1[4][4];
#pragma unroll
    for (int i = 0; i < 4; i++) {
#pragma unroll
        for (int j = 0; j < 4; j++) {
            float x00 = xv[2*i][2*j],   x01 = xv[2*i][2*j+1];
            float x10 = xv[2*i+1][2*j], x11 = xv[2*i+1][2*j+1];
            float s0 = x00 + x01, s1 = x10 + x11;
            float d0 = x01 - x00, d1 = x11 - x10;
            ll1[i][j] = (s0 + s1) * 0.5f;
            mx[0] = fmaxf(mx[0], fabsf((s1 - s0) * 0.5f));
            mx[1] = fmaxf(mx[1], fabsf((d0 + d1) * 0.5f));
            mx[2] = fmaxf(mx[2], fabsf((d1 - d0) * 0.5f));
        }
    }
    float ll2[2][2];
#pragma unroll
    for (int i = 0; i < 2; i++) {
#pragma unroll
        for (int j = 0; j < 2; j++) {
            float x00 = ll1[2*i][2*j],   x01 = ll1[2*i][2*j+1];
            float x10 = ll1[2*i+1][2*j], x11 = ll1[2*i+1][2*j+1];
            float s0 = x00 + x01, s1 = x10 + x11;
            float d0 = x01 - x00, d1 = x11 - x10;
            ll2[i][j] = (s0 + s1) * 0.5f;
            mx[3] = fmaxf(mx[3], fabsf((s1 - s0) * 0.5f));
            mx[4] = fmaxf(mx[4], fabsf((d0 + d1) * 0.5f));
            mx[5] = fmaxf(mx[5], fabsf((d1 - d0) * 0.5f));
        }
    }
    {
        float x00 = ll2[0][0], x01 = ll2[0][1];
        float x10 = ll2[1][0], x11 = ll2[1][1];
        float s0 = x00 + x01, s1 = x10 + x11;
        float d0 = x01 - x00, d1 = x11 - x10;
        mx[6] = fmaxf(mx[6], fabsf((s1 - s0) * 0.5f));
        mx[7] = fmaxf(mx[7], fabsf((d0 + d1) * 0.5f));
        mx[8] = fmaxf(mx[8], fabsf((d1 - d0) * 0.5f));
    }
}

// ---------------------------------------------------------------------------
// Probe (33 blocks): blocks 0..31 each probe 256 CONSECUTIVE tiles starting
// at b*chunk (coalesced within warps, chunks spread across the tensor).
// Block 32 zeroes g_absmax. Slots plain-stored -> replay-safe without init.
// ---------------------------------------------------------------------------
__global__ __launch_bounds__(256) void wt_probe(const float* __restrict__ x,
                                                int total_tiles, int chunk) {
    if (blockIdx.x == PROBE_BLOCKS) {
        if (threadIdx.x < 9) g_absmax[threadIdx.x] = 0;
        return;
    }
    int t = blockIdx.x * chunk + threadIdx.x;   // 256 consecutive tiles/block
    unsigned mask = 0;
    if (t < total_tiles) {
        int tx = t % TX;
        int r  = t / TX;
        int ty = r % TY;
        int bc = r / TY;
        const float* xp = x + (size_t)bc * (HDIM * WDIM)
                            + (size_t)(ty * 8) * WDIM + tx * 8;
        float xv[8][8];
        load_tile(xp, xv);
        float mx[9];
#pragma unroll
        for (int k = 0; k < 9; k++) mx[k] = 0.0f;
        tile_submax(xv, mx);
        const float thr[9] = {0.25f, 0.25f, 0.25f, 0.5f, 0.5f, 0.5f, 1.0f, 1.0f, 1.0f};
#pragma unroll
        for (int k = 0; k < 9; k++)
            if (mx[k] > thr[k]) mask |= (1u << k);
    }
    __shared__ unsigned swor[8];
    mask = warp_or(mask);
    int wid = threadIdx.x >> 5;
    if ((threadIdx.x & 31) == 0) swor[wid] = mask;
    __syncthreads();
    if (threadIdx.x == 0) {
        unsigned m = swor[0];
#pragma unroll
        for (int w = 1; w < 8; w++) m |= swor[w];
        g_probe[blockIdx.x] = m;   // overwrite: deterministic per launch
    }
}

// ---------------------------------------------------------------------------
// Main: fast path (all gates confirmed) reads only odd rows, writes 2*x11.
// Slow path: full scan, absmax reduction, speculative write.
// ---------------------------------------------------------------------------
__global__ __launch_bounds__(256, 2) void wt_main(const float* __restrict__ x,
                                                  float* __restrict__ out,
                                                  int total_tiles) {
    __shared__ unsigned sconf;
    bool fast = conf_all(&sconf);
    int t = blockIdx.x * 256 + threadIdx.x;

    if (fast) {
        if (t >= total_tiles) return;
        int tx = t % TX;
        int r  = t / TX;
        int ty = r % TY;
        int bc = r / TY;
        const float* xp = x + (size_t)bc * (HDIM * WDIM)
                            + (size_t)(ty * 8) * WDIM + tx * 8;
        float* op = out + (size_t)bc * (OH * OW)
                        + (size_t)(ty * 4) * OW + tx * 4;
#pragma unroll
        for (int rr = 0; rr < 4; rr++) {
            const float* rp = xp + (size_t)(2 * rr + 1) * WDIM;
            float4 a = *reinterpret_cast<const float4*>(rp);
            float4 b = *reinterpret_cast<const float4*>(rp + 4);
            float4 o;
            o.x = 2.0f * a.y;
            o.y = 2.0f * a.w;
            o.z = 2.0f * b.y;
            o.w = 2.0f * b.w;
            *reinterpret_cast<float4*>(op + rr * OW) = o;
        }
        return;
    }

    // ---- slow path: exact global abs-max + speculative write ----
    float mx[9];
#pragma unroll
    for (int k = 0; k < 9; k++) mx[k] = 0.0f;

    if (t < total_tiles) {
        int tx = t % TX;
        int r  = t / TX;
        int ty = r % TY;
        int bc = r / TY;
        const float* xp = x + (size_t)bc * (HDIM * WDIM)
                            + (size_t)(ty * 8) * WDIM + tx * 8;
        float xv[8][8];
        load_tile(xp, xv);

        float* op = out + (size_t)bc * (OH * OW)
                        + (size_t)(ty * 4) * OW + tx * 4;
#pragma unroll
        for (int rr = 0; rr < 4; rr++) {
            float4 o;
            o.x = 2.0f * xv[2*rr+1][1];
            o.y = 2.0f * xv[2*rr+1][3];
            o.z = 2.0f * xv[2*rr+1][5];
            o.w = 2.0f * xv[2*rr+1][7];
            *reinterpret_cast<float4*>(op + rr * OW) = o;
        }
        tile_submax(xv, mx);
    }

    __shared__ float sred[9][8];
    int wid = threadIdx.x >> 5;
    int lid = threadIdx.x & 31;
#pragma unroll
    for (int k = 0; k < 9; k++) {
        float v = warp_max(mx[k]);
        if (lid == 0) sred[k][wid] = v;
    }
    __syncthreads();
    if (threadIdx.x < 9) {
        float v = sred[threadIdx.x][0];
#pragma unroll
        for (int w = 1; w < 8; w++) v = fmaxf(v, sred[threadIdx.x][w]);
        atomicMax(&g_absmax[threadIdx.x], __float_as_int(v));
    }
}

// ---------------------------------------------------------------------------
// Pass 2 (grid-stride, small grid): no-op on confirmed fast path. Else gates
// from exact absmax; if all raw gates true the speculative write stands;
// otherwise reconstruct exactly.
// ---------------------------------------------------------------------------
__global__ __launch_bounds__(256) void wt_pass2(const float* __restrict__ x,
                                                float* __restrict__ out,
                                                int total_tiles) {
    __shared__ unsigned sconf;
    if (conf_all(&sconf)) return;

    bool r1lh = __int_as_float(g_absmax[0]) > 0.25f;
    bool r1hl = __int_as_float(g_absmax[1]) > 0.25f;
    bool r1hh = __int_as_float(g_absmax[2]) > 0.25f;
    bool r2lh = __int_as_float(g_absmax[3]) > 0.5f;
    bool r2hl = __int_as_float(g_absmax[4]) > 0.5f;
    bool r2hh = __int_as_float(g_absmax[5]) > 0.5f;
    bool r3lh = __int_as_float(g_absmax[6]) > 1.0f;
    bool r3hl = __int_as_float(g_absmax[7]) > 1.0f;
    bool r3hh = __int_as_float(g_absmax[8]) > 1.0f;

    if (r1lh && r1hl && r1hh && r2lh && r2hl && r2hh && r3lh && r3hl && r3hh)
        return;  // speculative write from wt_main slow path is exact

    float G3lh = r3lh ? 1.0f : 0.0f;
    float G3hl = r3hl ? 1.0f : 0.0f;
    float G3hh = r3hh ? 1.0f : 0.0f;
    float G2lh = (r2lh && r3lh) ? 1.0f : 0.0f;
    float G2hl = (r2hl && r3hl) ? 1.0f : 0.0f;
    float G2hh = (r2hh && r3hh) ? 1.0f : 0.0f;
    float G1lh = (r1lh && r2lh && r3lh) ? 1.0f : 0.0f;
    float G1hl = (r1hl && r2hl && r3hl) ? 1.0f : 0.0f;
    float G1hh = (r1hh && r2hh && r3hh) ? 1.0f : 0.0f;

    for (int t = blockIdx.x * 256 + threadIdx.x; t < total_tiles;
         t += gridDim.x * 256) {
        int tx = t % TX;
        int r  = t / TX;
        int ty = r % TY;
        int bc = r / TY;

        const float* xp = x + (size_t)bc * (HDIM * WDIM)
                            + (size_t)(ty * 8) * WDIM + tx * 8;
        float xv[8][8];
        load_tile(xp, xv);

        float ll1[4][4];
#pragma unroll
        for (int i = 0; i < 4; i++) {
#pragma unroll
            for (int j = 0; j < 4; j++) {
                float x00 = xv[2*i][2*j],   x01 = xv[2*i][2*j+1];
                float x10 = xv[2*i+1][2*j], x11 = xv[2*i+1][2*j+1];
                ll1[i][j] = ((x00 + x01) + (x10 + x11)) * 0.5f;
            }
        }

        float ll2[2][2], lh2[2][2], hl2[2][2], hh2[2][2];
#pragma unroll
        for (int i = 0; i < 2; i++) {
#pragma unroll
            for (int j = 0; j < 2; j++) {
                float x00 = ll1[2*i][2*j],   x01 = ll1[2*i][2*j+1];
                float x10 = ll1[2*i+1][2*j], x11 = ll1[2*i+1][2*j+1];
                float s0 = x00 + x01, s1 = x10 + x11;
                float d0 = x01 - x00, d1 = x11 - x10;
                ll2[i][j] = (s0 + s1) * 0.5f;
                lh2[i][j] = (s1 - s0) * 0.5f;
                hl2[i][j] = (d0 + d1) * 0.5f;
                hh2[i][j] = (d1 - d0) * 0.5f;
            }
        }

        float ll3, lh3, hl3, hh3;
        {
            float x00 = ll2[0][0], x01 = ll2[0][1];
            float x10 = ll2[1][0], x11 = ll2[1][1];
            float s0 = x00 + x01, s1 = x10 + x11;
            float d0 = x01 - x00, d1 = x11 - x10;
            ll3 = (s0 + s1) * 0.5f;
            lh3 = (s1 - s0) * 0.5f;
            hl3 = (d0 + d1) * 0.5f;
            hh3 = (d1 - d0) * 0.5f;
        }

        float r2v[2][2];
        {
            float a = ll3, b = G3lh * lh3, c = G3hl * hl3, d = G3hh * hh3;
            r2v[0][0] = (a - b - c + d) * 0.5f;
            r2v[0][1] = (a - b + c - d) * 0.5f;
            r2v[1][0] = (a + b - c - d) * 0.5f;
            r2v[1][1] = (a + b + c + d) * 0.5f;
        }

        float r1v[4][4];
#pragma unroll
        for (int i = 0; i < 2; i++) {
#pragma unroll
            for (int j = 0; j < 2; j++) {
                float a = r2v[i][j];
                float b = G2lh * lh2[i][j];
                float c = G2hl * hl2[i][j];
                float d = G2hh * hh2[i][j];
                r1v[2*i][2*j]     = (a - b - c + d) * 0.5f;
                r1v[2*i][2*j+1]   = (a - b + c - d) * 0.5f;
                r1v[2*i+1][2*j]   = (a + b - c - d) * 0.5f;
                r1v[2*i+1][2*j+1] = (a + b + c + d) * 0.5f;
            }
        }

        float* op = out + (size_t)bc * (OH * OW)
                        + (size_t)(ty * 4) * OW + tx * 4;
#pragma unroll
        for (int i = 0; i < 4; i++) {
            float row[4];
#pragma unroll
            for (int j = 0; j < 4; j++) {
                float x00 = xv[2*i][2*j],   x01 = xv[2*i][2*j+1];
                float x10 = xv[2*i+1][2*j], x11 = xv[2*i+1][2*j+1];
                float s0 = x00 + x01, s1 = x10 + x11;
                float d0 = x01 - x00, d1 = x11 - x10;
                float lh1 = (s1 - s0) * 0.5f;
                float hl1 = (d0 + d1) * 0.5f;
                float hh1 = (d1 - d0) * 0.5f;
                row[j] = r1v[i][j] + G1lh * lh1 + G1hl * hl1 + G1hh * hh1;
            }
            float4 o; o.x = row[0]; o.y = row[1]; o.z = row[2]; o.w = row[3];
            *reinterpret_cast<float4*>(op + i * OW) = o;
        }
    }
}

extern "C" void kernel_launch(void* const* d_in, const int* in_sizes, int n_in,
                              void* d_out, int out_size) {
    const float* x = (const float*)d_in[0];
    float* out = (float*)d_out;

    int n  = in_sizes[0];
    int bc = n / (HDIM * WDIM);          // B*C planes
    int total_tiles = bc * TPB;
    int blocks = (total_tiles + 255) / 256;

    int chunk = total_tiles / PROBE_BLOCKS;
    if (chunk < 256) chunk = 256;

    wt_probe<<<PROBE_BLOCKS + 1, 256>>>(x, total_tiles, chunk);
    wt_main<<<blocks, 256>>>(x, out, total_tiles);
    wt_pass2<<<P2_BLOCKS, 256>>>(x, out, total_tiles);
}

// round 5
// speedup vs baseline: 1.4181x; 1.0049x over previous
#include <cuda_runtime.h>

// WaveletTree: 3-level gated Haar DWT/IDWT tree.
// x: [B,C,224,224] f32 -> out: [B,C,112,112] f32.
// Gate = (max|subband| > thr) is an existence test: a sparse probe can CONFIRM
// gates without a full scan. With all 9 gates confirmed, idwt(dwt) telescopes:
// out = 2*x[:,:,1::2,1::2] exactly, needing only odd input rows (half read).
// Probe: 64 blocks x 256 consecutive tiles each (coalesced, spread chunks) --
// sized to occupy many SMs since the probe is latency-bound, not BW-bound.

namespace {
constexpr int HDIM = 224;
constexpr int WDIM = 224;
constexpr int OH   = 112;
constexpr int OW   = 112;
constexpr int TX   = 28;       // tiles per row (224/8)
constexpr int TY   = 28;
constexpr int TPB  = TX * TY;  // tiles per (b,c) plane
constexpr int PROBE_BLOCKS  = 64;
constexpr unsigned ALL_CONF = 0x1FFu;  // 9 gates
constexpr int P2_BLOCKS = 592;         // grid-stride pass2
}

// order: [lh1, hl1, hh1, lh2, hl2, hh2, lh3, hl3, hh3]
__device__ int g_absmax[9];                 // float bits as int (non-neg)
__device__ unsigned g_probe[PROBE_BLOCKS];  // per-block masks (overwritten)

__device__ __forceinline__ float warp_max(float v) {
#pragma unroll
    for (int o = 16; o; o >>= 1)
        v = fmaxf(v, __shfl_xor_sync(0xffffffffu, v, o));
    return v;
}

__device__ __forceinline__ unsigned warp_or(unsigned m) {
#pragma unroll
    for (int o = 16; o; o >>= 1)
        m |= __shfl_xor_sync(0xffffffffu, m, o);
    return m;
}

// Combined probe mask from the 64 slots (L2 hits after first block).
__device__ __forceinline__ bool conf_all(unsigned* sconf_shared) {
    if (threadIdx.x < 32) {
        unsigned m = g_probe[threadIdx.x] | g_probe[threadIdx.x + 32];
        m = warp_or(m);
        if (threadIdx.x == 0) *sconf_shared = m;
    }
    __syncthreads();
    return (*sconf_shared == ALL_CONF);
}

__device__ __forceinline__ void load_tile(const float* __restrict__ xp,
                                          float xv[8][8]) {
#pragma unroll
    for (int rr = 0; rr < 8; rr++) {
        float4 a = *reinterpret_cast<const float4*>(xp + rr * WDIM);
        float4 b = *reinterpret_cast<const float4*>(xp + rr * WDIM + 4);
        xv[rr][0] = a.x; xv[rr][1] = a.y; xv[rr][2] = a.z; xv[rr][3] = a.w;
        xv[rr][4] = b.x; xv[rr][5] = b.y; xv[rr][6] = b.z; xv[rr][7] = b.w;
    }
}

// 9 per-tile subband abs-maxes from an 8x8 tile in registers.
__device__ __forceinline__ void tile_submax(const float xv[8][8], float mx[9]) {
    float ll1[4][4];
#pragma unroll
    for (int i = 0; i < 4; i++) {
#pragma unroll
        for (int j = 0; j < 4; j++) {
            float x00 = xv[2*i][2*j],   x01 = xv[2*i][2*j+1];
            float x10 = xv[2*i+1][2*j], x11 = xv[2*i+1][2*j+1];
            float s0 = x00 + x01, s1 = x10 + x11;
            float d0 = x01 - x00, d1 = x11 - x10;
            ll1[i][j] = (s0 + s1) * 0.5f;
            mx[0] = fmaxf(mx[0], fabsf((s1 - s0) * 0.5f));
            mx[1] = fmaxf(mx[1], fabsf((d0 + d1) * 0.5f));
            mx[2] = fmaxf(mx[2], fabsf((d1 - d0) * 0.5f));
        }
    }
    float ll2[2][2];
#pragma unroll
    for (int i = 0; i < 2; i++) {
#pragma unroll
        for (int j = 0; j < 2; j++) {
            float x00 = ll1[2*i][2*j],   x01 = ll1[2*i][2*j+1];
            float x10 = ll1[2*i+1][2*j], x11 = ll1[2*i+1][2*j+1];
            float s0 = x00 + x01, s1 = x10 + x11;
            float d0 = x01 - x00, d1 = x11 - x10;
            ll2[i][j] = (s0 + s1) * 0.5f;
            mx[3] = fmaxf(mx[3], fabsf((s1 - s0) * 0.5f));
            mx[4] = fmaxf(mx[4], fabsf((d0 + d1) * 0.5f));
            mx[5] = fmaxf(mx[5], fabsf((d1 - d0) * 0.5f));
        }
    }
    {
        float x00 = ll2[0][0], x01 = ll2[0][1];
        float x10 = ll2[1][0], x11 = ll2[1][1];
        float s0 = x00 + x01, s1 = x10 + x11;
        float d0 = x01 - x00, d1 = x11 - x10;
        mx[6] = fmaxf(mx[6], fabsf((s1 - s0) * 0.5f));
        mx[7] = fmaxf(mx[7], fabsf((d0 + d1) * 0.5f));
        mx[8] = fmaxf(mx[8], fabsf((d1 - d0) * 0.5f));
    }
}

// ---------------------------------------------------------------------------
// Probe (65 blocks): blocks 0..63 each probe 256 CONSECUTIVE tiles starting
// at b*chunk (coalesced within warps; chunks spread across the tensor).
// Block 64 zeroes g_absmax. Slots plain-stored -> replay-safe without init.
// ---------------------------------------------------------------------------
__global__ __launch_bounds__(256) void wt_probe(const float* __restrict__ x,
                                                int total_tiles, int chunk) {
    if (blockIdx.x == PROBE_BLOCKS) {
        if (threadIdx.x < 9) g_absmax[threadIdx.x] = 0;
        return;
    }
    int t = blockIdx.x * chunk + threadIdx.x;   // 256 consecutive tiles/block
    unsigned mask = 0;
    if (t < total_tiles) {
        int tx = t % TX;
        int r  = t / TX;
        int ty = r % TY;
        int bc = r / TY;
        const float* xp = x + (size_t)bc * (HDIM * WDIM)
                            + (size_t)(ty * 8) * WDIM + tx * 8;
        float xv[8][8];
        load_tile(xp, xv);
        float mx[9];
#pragma unroll
        for (int k = 0; k < 9; k++) mx[k] = 0.0f;
        tile_submax(xv, mx);
        const float thr[9] = {0.25f, 0.25f, 0.25f, 0.5f, 0.5f, 0.5f, 1.0f, 1.0f, 1.0f};
#pragma unroll
        for (int k = 0; k < 9; k++)
            if (mx[k] > thr[k]) mask |= (1u << k);
    }
    __shared__ unsigned swor[8];
    mask = warp_or(mask);
    int wid = threadIdx.x >> 5;
    if ((threadIdx.x & 31) == 0) swor[wid] = mask;
    __syncthreads();
    if (threadIdx.x == 0) {
        unsigned m = swor[0];
#pragma unroll
        for (int w = 1; w < 8; w++) m |= swor[w];
        g_probe[blockIdx.x] = m;   // overwrite: deterministic per launch
    }
}

// ---------------------------------------------------------------------------
// Main: fast path (all gates confirmed) reads only odd rows, writes 2*x11.
// Slow path: full scan, absmax reduction, speculative write.
// ---------------------------------------------------------------------------
__global__ __launch_bounds__(256, 2) void wt_main(const float* __restrict__ x,
                                                  float* __restrict__ out,
                                                  int total_tiles) {
    __shared__ unsigned sconf;
    bool fast = conf_all(&sconf);
    int t = blockIdx.x * 256 + threadIdx.x;

    if (fast) {
        if (t >= total_tiles) return;
        int tx = t % TX;
        int r  = t / TX;
        int ty = r % TY;
        int bc = r / TY;
        const float* xp = x + (size_t)bc * (HDIM * WDIM)
                            + (size_t)(ty * 8) * WDIM + tx * 8;
        float* op = out + (size_t)bc * (OH * OW)
                        + (size_t)(ty * 4) * OW + tx * 4;
#pragma unroll
        for (int rr = 0; rr < 4; rr++) {
            const float* rp = xp + (size_t)(2 * rr + 1) * WDIM;
            float4 a = *reinterpret_cast<const float4*>(rp);
            float4 b = *reinterpret_cast<const float4*>(rp + 4);
            float4 o;
            o.x = 2.0f * a.y;
            o.y = 2.0f * a.w;
            o.z = 2.0f * b.y;
            o.w = 2.0f * b.w;
            *reinterpret_cast<float4*>(op + rr * OW) = o;
        }
        return;
    }

    // ---- slow path: exact global abs-max + speculative write ----
    float mx[9];
#pragma unroll
    for (int k = 0; k < 9; k++) mx[k] = 0.0f;

    if (t < total_tiles) {
        int tx = t % TX;
        int r  = t / TX;
        int ty = r % TY;
        int bc = r / TY;
        const float* xp = x + (size_t)bc * (HDIM * WDIM)
                            + (size_t)(ty * 8) * WDIM + tx * 8;
        float xv[8][8];
        load_tile(xp, xv);

        float* op = out + (size_t)bc * (OH * OW)
                        + (size_t)(ty * 4) * OW + tx * 4;
#pragma unroll
        for (int rr = 0; rr < 4; rr++) {
            float4 o;
            o.x = 2.0f * xv[2*rr+1][1];
            o.y = 2.0f * xv[2*rr+1][3];
            o.z = 2.0f * xv[2*rr+1][5];
            o.w = 2.0f * xv[2*rr+1][7];
            *reinterpret_cast<float4*>(op + rr * OW) = o;
        }
        tile_submax(xv, mx);
    }

    __shared__ float sred[9][8];
    int wid = threadIdx.x >> 5;
    int lid = threadIdx.x & 31;
#pragma unroll
    for (int k = 0; k < 9; k++) {
        float v = warp_max(mx[k]);
        if (lid == 0) sred[k][wid] = v;
    }
    __syncthreads();
    if (threadIdx.x < 9) {
        float v = sred[threadIdx.x][0];
#pragma unroll
        for (int w = 1; w < 8; w++) v = fmaxf(v, sred[threadIdx.x][w]);
        atomicMax(&g_absmax[threadIdx.x], __float_as_int(v));
    }
}

// ---------------------------------------------------------------------------
// Pass 2 (grid-stride, small grid): no-op on confirmed fast path. Else gates
// from exact absmax; if all raw gates true the speculative write stands;
// otherwise reconstruct exactly.
// ---------------------------------------------------------------------------
__global__ __launch_bounds__(256) void wt_pass2(const float* __restrict__ x,
                                                float* __restrict__ out,
                                                int total_tiles) {
    __shared__ unsigned sconf;
    if (conf_all(&sconf)) return;

    bool r1lh = __int_as_float(g_absmax[0]) > 0.25f;
    bool r1hl = __int_as_float(g_absmax[1]) > 0.25f;
    bool r1hh = __int_as_float(g_absmax[2]) > 0.25f;
    bool r2lh = __int_as_float(g_absmax[3]) > 0.5f;
    bool r2hl = __int_as_float(g_absmax[4]) > 0.5f;
    bool r2hh = __int_as_float(g_absmax[5]) > 0.5f;
    bool r3lh = __int_as_float(g_absmax[6]) > 1.0f;
    bool r3hl = __int_as_float(g_absmax[7]) > 1.0f;
    bool r3hh = __int_as_float(g_absmax[8]) > 1.0f;

    if (r1lh && r1hl && r1hh && r2lh && r2hl && r2hh && r3lh && r3hl && r3hh)
        return;  // speculative write from wt_main slow path is exact

    float G3lh = r3lh ? 1.0f : 0.0f;
    float G3hl = r3hl ? 1.0f : 0.0f;
    float G3hh = r3hh ? 1.0f : 0.0f;
    float G2lh = (r2lh && r3lh) ? 1.0f : 0.0f;
    float G2hl = (r2hl && r3hl) ? 1.0f : 0.0f;
    float G2hh = (r2hh && r3hh) ? 1.0f : 0.0f;
    float G1lh = (r1lh && r2lh && r3lh) ? 1.0f : 0.0f;
    float G1hl = (r1hl && r2hl && r3hl) ? 1.0f : 0.0f;
    float G1hh = (r1hh && r2hh && r3hh) ? 1.0f : 0.0f;

    for (int t = blockIdx.x * 256 + threadIdx.x; t < total_tiles;
         t += gridDim.x * 256) {
        int tx = t % TX;
        int r  = t / TX;
        int ty = r % TY;
        int bc = r / TY;

        const float* xp = x + (size_t)bc * (HDIM * WDIM)
                            + (size_t)(ty * 8) * WDIM + tx * 8;
        float xv[8][8];
        load_tile(xp, xv);

        float ll1[4][4];
#pragma unroll
        for (int i = 0; i < 4; i++) {
#pragma unroll
            for (int j = 0; j < 4; j++) {
                float x00 = xv[2*i][2*j],   x01 = xv[2*i][2*j+1];
                float x10 = xv[2*i+1][2*j], x11 = xv[2*i+1][2*j+1];
                ll1[i][j] = ((x00 + x01) + (x10 + x11)) * 0.5f;
            }
        }

        float ll2[2][2], lh2[2][2], hl2[2][2], hh2[2][2];
#pragma unroll
        for (int i = 0; i < 2; i++) {
#pragma unroll
            for (int j = 0; j < 2; j++) {
                float x00 = ll1[2*i][2*j],   x01 = ll1[2*i][2*j+1];
                float x10 = ll1[2*i+1][2*j], x11 = ll1[2*i+1][2*j+1];
                float s0 = x00 + x01, s1 = x10 + x11;
                float d0 = x01 - x00, d1 = x11 - x10;
                ll2[i][j] = (s0 + s1) * 0.5f;
                lh2[i][j] = (s1 - s0) * 0.5f;
                hl2[i][j] = (d0 + d1) * 0.5f;
                hh2[i][j] = (d1 - d0) * 0.5f;
            }
        }

        float ll3, lh3, hl3, hh3;
        {
            float x00 = ll2[0][0], x01 = ll2[0][1];
            float x10 = ll2[1][0], x11 = ll2[1][1];
            float s0 = x00 + x01, s1 = x10 + x11;
            float d0 = x01 - x00, d1 = x11 - x10;
            ll3 = (s0 + s1) * 0.5f;
            lh3 = (s1 - s0) * 0.5f;
            hl3 = (d0 + d1) * 0.5f;
            hh3 = (d1 - d0) * 0.5f;
        }

        float r2v[2][2];
        {
            float a = ll3, b = G3lh * lh3, c = G3hl * hl3, d = G3hh * hh3;
            r2v[0][0] = (a - b - c + d) * 0.5f;
            r2v[0][1] = (a - b + c - d) * 0.5f;
            r2v[1][0] = (a + b - c - d) * 0.5f;
            r2v[1][1] = (a + b + c + d) * 0.5f;
        }

        float r1v[4][4];
#pragma unroll
        for (int i = 0; i < 2; i++) {
#pragma unroll
            for (int j = 0; j < 2; j++) {
                float a = r2v[i][j];
                float b = G2lh * lh2[i][j];
                float c = G2hl * hl2[i][j];
                float d = G2hh * hh2[i][j];
                r1v[2*i][2*j]     = (a - b - c + d) * 0.5f;
                r1v[2*i][2*j+1]   = (a - b + c - d) * 0.5f;
                r1v[2*i+1][2*j]   = (a + b - c - d) * 0.5f;
                r1v[2*i+1][2*j+1] = (a + b + c + d) * 0.5f;
            }
        }

        float* op = out + (size_t)bc * (OH * OW)
                        + (size_t)(ty * 4) * OW + tx * 4;
#pragma unroll
        for (int i = 0; i < 4; i++) {
            float row[4];
#pragma unroll
            for (int j = 0; j < 4; j++) {
                float x00 = xv[2*i][2*j],   x01 = xv[2*i][2*j+1];
                float x10 = xv[2*i+1][2*j], x11 = xv[2*i+1][2*j+1];
                float s0 = x00 + x01, s1 = x10 + x11;
                float d0 = x01 - x00, d1 = x11 - x10;
                float lh1 = (s1 - s0) * 0.5f;
                float hl1 = (d0 + d1) * 0.5f;
                float hh1 = (d1 - d0) * 0.5f;
                row[j] = r1v[i][j] + G1lh * lh1 + G1hl * hl1 + G1hh * hh1;
            }
            float4 o; o.x = row[0]; o.y = row[1]; o.z = row[2]; o.w = row[3];
            *reinterpret_cast<float4*>(op + i * OW) = o;
        }
    }
}

extern "C" void kernel_launch(void* const* d_in, const int* in_sizes, int n_in,
                              void* d_out, int out_size) {
    const float* x = (const float*)d_in[0];
    float* out = (float*)d_out;

    int n  = in_sizes[0];
    int bc = n / (HDIM * WDIM);          // B*C planes
    int total_tiles = bc * TPB;
    int blocks = (total_tiles + 255) / 256;

    int chunk = total_tiles / PROBE_BLOCKS;
    if (chunk < 256) chunk = 256;

    wt_probe<<<PROBE_BLOCKS + 1, 256>>>(x, total_tiles, chunk);
    wt_main<<<blocks, 256>>>(x, out, total_tiles);
    wt_pass2<<<P2_BLOCKS, 256>>>(x, out, total_tiles);
}